// round 12
// baseline (speedup 1.0000x reference)
#include <cuda_runtime.h>
#include <cuda_fp16.h>
#include <cstdint>
#include <cstddef>

#define NNODES 100000
#define NPAD   100096           // 782 * 128
#define NEDGES 1600000
#define NBM    782              // NPAD / 128
#define SCAN_BLOCKS 98          // 98 * 1024 >= NNODES

// ---------------- scratch (device globals) ----------------
__device__ __align__(16) __half g_p  [(size_t)NPAD * 128];   // h @ W2l^T in fp16
__device__ __align__(16) __half g_xh [(size_t)NNODES * 128]; // x in fp16
__device__ __align__(16) __half g_a  [(size_t)NPAD * 256];   // layer1 input fp16
__device__ __align__(16) __half g_b  [(size_t)NPAD * 256];   // layer2 input fp16
__device__ __align__(16) __half g_w1hi[256 * 256];
__device__ __align__(16) __half g_w1lo[256 * 256];
__device__ __align__(16) __half g_w2hi[256 * 256];
__device__ __align__(16) __half g_w2lo[256 * 256];
__device__ int g_rowptr[NNODES + 1];
__device__ int g_wix[NNODES];
__device__ int g_srcidx[NEDGES];
__device__ int g_bsum[SCAN_BLOCKS];
__device__ int g_boff[SCAN_BLOCKS];
__device__ int g_is64;

__device__ __forceinline__ uint32_t smem_u32(const void* p) {
    uint32_t a;
    asm("{ .reg .u64 t; cvta.to.shared.u64 t, %1; cvt.u32.u64 %0, t; }"
        : "=r"(a) : "l"(p));
    return a;
}

#define MMA_F16(c, a, b0, b1) \
    asm volatile("mma.sync.aligned.m16n8k16.row.col.f32.f16.f16.f32 " \
        "{%0,%1,%2,%3}, {%4,%5,%6,%7}, {%8,%9}, {%0,%1,%2,%3};" \
        : "+f"((c)[0]), "+f"((c)[1]), "+f"((c)[2]), "+f"((c)[3]) \
        : "r"((a)[0]), "r"((a)[1]), "r"((a)[2]), "r"((a)[3]), "r"(b0), "r"(b1))

#define CP_ASYNC16(dst, src) \
    asm volatile("cp.async.cg.shared.global [%0], [%1], 16;" \
                 :: "r"(dst), "l"(src) : "memory")
#define CP_COMMIT() asm volatile("cp.async.commit_group;" ::: "memory")
#define CP_WAIT0()  asm volatile("cp.async.wait_group 0;" ::: "memory")

// ---------------- edge index decode ----------------
__device__ __forceinline__ void load_edge(const void* ei, int e, int& s, int& t) {
    if (g_is64) {
        const long long* e64 = (const long long*)ei;
        s = (int)e64[e];
        t = (int)e64[(size_t)NEDGES + e];
    } else {
        const int* e32 = (const int*)ei;
        s = e32[e];
        t = e32[(size_t)NEDGES + e];
    }
}

__global__ void detect_kernel(const int* __restrict__ ei32) {
    __shared__ int sOr;
    if (threadIdx.x == 0) sOr = 0;
    __syncthreads();
    int acc = 0;
    for (int i = threadIdx.x; i < 2048; i += blockDim.x) acc |= ei32[2 * i + 1];
    atomicOr(&sOr, acc);
    __syncthreads();
    if (threadIdx.x == 0) g_is64 = (sOr == 0) ? 1 : 0;
}

// ---------------- CSR build (by target) ----------------
__global__ void zero_wix() {
    int i = blockIdx.x * blockDim.x + threadIdx.x;
    if (i < NNODES) g_wix[i] = 0;
}

__global__ void count_kernel(const void* __restrict__ ei) {
    int e = blockIdx.x * blockDim.x + threadIdx.x;
    if (e >= NEDGES) return;
    int s, t;
    load_edge(ei, e, s, t);
    if ((unsigned)s >= NNODES || (unsigned)t >= NNODES) return;
    atomicAdd(&g_wix[t], 1);
}

__global__ void blocksum_kernel() {
    __shared__ int red[32];
    int idx = blockIdx.x * 1024 + threadIdx.x;
    int v = (idx < NNODES) ? g_wix[idx] : 0;
#pragma unroll
    for (int o = 16; o > 0; o >>= 1) v += __shfl_down_sync(0xFFFFFFFFu, v, o);
    if ((threadIdx.x & 31) == 0) red[threadIdx.x >> 5] = v;
    __syncthreads();
    if (threadIdx.x < 32) {
        int w = red[threadIdx.x];
#pragma unroll
        for (int o = 16; o > 0; o >>= 1) w += __shfl_down_sync(0xFFFFFFFFu, w, o);
        if (threadIdx.x == 0) g_bsum[blockIdx.x] = w;
    }
}

__global__ void scan_bsum() {
    __shared__ int s[SCAN_BLOCKS];
    int tid = threadIdx.x;
    if (tid < SCAN_BLOCKS) s[tid] = g_bsum[tid];
    __syncthreads();
    if (tid == 0) {
        int run = 0;
        for (int i = 0; i < SCAN_BLOCKS; ++i) {
            g_boff[i] = run;
            run += s[i];
        }
        g_rowptr[NNODES] = run;
    }
}

__global__ void rowptr_kernel() {
    __shared__ int sc[1024];
    int tid = threadIdx.x;
    int idx = blockIdx.x * 1024 + tid;
    int v = (idx < NNODES) ? g_wix[idx] : 0;
    sc[tid] = v;
    __syncthreads();
#pragma unroll
    for (int off = 1; off < 1024; off <<= 1) {
        int u = (tid >= off) ? sc[tid - off] : 0;
        __syncthreads();
        sc[tid] += u;
        __syncthreads();
    }
    if (idx < NNODES) {
        int excl = sc[tid] - v + g_boff[blockIdx.x];
        g_rowptr[idx] = excl;
        g_wix[idx] = excl;
    }
}

__global__ void scatter_kernel(const void* __restrict__ ei) {
    int e = blockIdx.x * blockDim.x + threadIdx.x;
    if (e >= NEDGES) return;
    int s, t;
    load_edge(ei, e, s, t);
    if ((unsigned)s >= NNODES || (unsigned)t >= NNODES) return;
    int pos = atomicAdd(&g_wix[t], 1);
    g_srcidx[pos] = s;
}

// ---------------- x -> fp16 convert ----------------
__global__ void xconv_kernel(const float* __restrict__ x) {
    int idx = blockIdx.x * 256 + threadIdx.x;   // float4 index, NNODES*32 total
    if (idx >= NNODES * 32) return;
    float4 v = ((const float4*)x)[idx];
    __half hm[4] = {__float2half(v.x), __float2half(v.y),
                    __float2half(v.z), __float2half(v.w)};
    *(uint2*)(g_xh + (size_t)idx * 4) = *(const uint2*)hm;
}

// ---------------- gather: one warp per node, 2 neighbors in flight ----------------
// lane<16 processes even-list neighbors, lane>=16 odd-list; each lane loads
// 16B (8 fp16 cols). shfl_xor(16) folds the halves at the end.
// phase 0: mean -> g_a cols [0,128); g_xh[node] copy -> cols [128,256)
// phase 1: mean of g_p -> out[node] += mean
__global__ void gather_kernel(float* __restrict__ out, int phase) {
    int node = (int)(((size_t)blockIdx.x * blockDim.x + threadIdx.x) >> 5);
    int lane = threadIdx.x & 31;
    if (node >= NNODES) return;
    int half = lane >> 4;       // 0 or 1
    int hl   = lane & 15;       // col group: cols [hl*8, hl*8+8)
    int beg = g_rowptr[node];
    int end = g_rowptr[node + 1];
    const __half* src = (phase == 0) ? g_xh : g_p;

    float a0 = 0.f, a1 = 0.f, a2 = 0.f, a3 = 0.f;
    float a4 = 0.f, a5 = 0.f, a6 = 0.f, a7 = 0.f;

#define ACC8(vv) do { \
        float2 f0 = __half22float2(*(const __half2*)&(vv).x); \
        float2 f1 = __half22float2(*(const __half2*)&(vv).y); \
        float2 f2 = __half22float2(*(const __half2*)&(vv).z); \
        float2 f3 = __half22float2(*(const __half2*)&(vv).w); \
        a0 += f0.x; a1 += f0.y; a2 += f1.x; a3 += f1.y; \
        a4 += f2.x; a5 += f2.y; a6 += f3.x; a7 += f3.y; } while (0)

    int i = beg;
    for (; i + 8 <= end; i += 8) {      // 4 pairs per iteration
        int n[4];
#pragma unroll
        for (int u = 0; u < 4; ++u) n[u] = g_srcidx[i + 2 * u + half];
        uint4 v[4];
#pragma unroll
        for (int u = 0; u < 4; ++u)
            v[u] = *(const uint4*)(src + ((size_t)n[u] << 7) + hl * 8);
#pragma unroll
        for (int u = 0; u < 4; ++u) ACC8(v[u]);
    }
    for (; i + 2 <= end; i += 2) {      // single pair
        int n0 = g_srcidx[i + half];
        uint4 v0 = *(const uint4*)(src + ((size_t)n0 << 7) + hl * 8);
        ACC8(v0);
    }
    if (i < end && half == 0) {          // odd leftover: half 0 only
        int n0 = g_srcidx[i];
        uint4 v0 = *(const uint4*)(src + ((size_t)n0 << 7) + hl * 8);
        ACC8(v0);
    }
#undef ACC8

    // fold the two halves
    a0 += __shfl_xor_sync(0xFFFFFFFFu, a0, 16);
    a1 += __shfl_xor_sync(0xFFFFFFFFu, a1, 16);
    a2 += __shfl_xor_sync(0xFFFFFFFFu, a2, 16);
    a3 += __shfl_xor_sync(0xFFFFFFFFu, a3, 16);
    a4 += __shfl_xor_sync(0xFFFFFFFFu, a4, 16);
    a5 += __shfl_xor_sync(0xFFFFFFFFu, a5, 16);
    a6 += __shfl_xor_sync(0xFFFFFFFFu, a6, 16);
    a7 += __shfl_xor_sync(0xFFFFFFFFu, a7, 16);

    float rdeg = 1.0f / fmaxf((float)(end - beg), 1.0f);

    if (phase == 0) {
        if (half == 0) {
            __half hm[8] = {__float2half(a0 * rdeg), __float2half(a1 * rdeg),
                            __float2half(a2 * rdeg), __float2half(a3 * rdeg),
                            __float2half(a4 * rdeg), __float2half(a5 * rdeg),
                            __float2half(a6 * rdeg), __float2half(a7 * rdeg)};
            *(uint4*)(g_a + (size_t)node * 256 + hl * 8) = *(const uint4*)hm;
            // fused xsplit: copy x[node] fp16 -> cols [128,256)
            uint4 xr = *(const uint4*)(g_xh + ((size_t)node << 7) + hl * 8);
            *(uint4*)(g_a + (size_t)node * 256 + 128 + hl * 8) = xr;
        }
    } else {
        if (half == 0) {
            float4* op = (float4*)out + (size_t)node * 32 + hl * 2;
            float4 o0 = op[0], o1 = op[1];
            o0.x += a0 * rdeg; o0.y += a1 * rdeg;
            o0.z += a2 * rdeg; o0.w += a3 * rdeg;
            o1.x += a4 * rdeg; o1.y += a5 * rdeg;
            o1.z += a6 * rdeg; o1.w += a7 * rdeg;
            op[0] = o0; op[1] = o1;
        }
    }
}

// zero the 96 pad rows of g_a (all 256 cols)
__global__ void pad_kernel() {
    int r = NNODES + blockIdx.x;            // 96 blocks
    int q = threadIdx.x;                     // 64 threads x 4 halves
    uint2 z = make_uint2(0u, 0u);
    *(uint2*)(g_a + (size_t)r * 256 + q * 4) = z;
}

__global__ void prep_weights(const float* __restrict__ W1l, const float* __restrict__ W1r,
                             const float* __restrict__ W2l, const float* __restrict__ W2r) {
    int j = blockIdx.x;    // out dim
    int k = threadIdx.x;   // in dim
    float w1 = (k < 128) ? W1l[j * 128 + k] : W1r[j * 128 + (k - 128)];
    float w2 = (j < 128) ? W2l[j * 256 + k] : W2r[(j - 128) * 256 + k];
    __half h1 = __float2half(w1);
    __half h2 = __float2half(w2);
    g_w1hi[j * 256 + k] = h1;
    g_w1lo[j * 256 + k] = __float2half(w1 - __half2float(h1));
    g_w2hi[j * 256 + k] = h2;
    g_w2lo[j * 256 + k] = __float2half(w2 - __half2float(h2));
}

// ---------------- mma.sync GEMM: 2-term fp16 (A single, W hi/lo) ----------------
#define TILE_B   10240      // 128 * 80
#define STAGE_B  30720
#define GEMM_SMEM 61440

__device__ __forceinline__ void cp_stage(uint32_t sb,
    const __half* A, const __half* Whi, const __half* Wlo,
    int row0, int nbase, int kt, int st, int tid) {
#pragma unroll
    for (int i = 0; i < 6; ++i) {
        int c = i * 256 + tid;          // 0..1535
        int tile = c >> 9;              // 0:A 1:Whi 2:Wlo
        int idx  = c & 511;
        int row  = idx >> 2;
        int kc   = idx & 3;
        uint32_t dst = sb + st * STAGE_B + tile * TILE_B
                     + (uint32_t)(row * 80 + kc * 16);
        const __half* g;
        if (tile == 0)      g = A   + (size_t)(row0 + row) * 256;
        else if (tile == 1) g = Whi + (size_t)(nbase + row) * 256;
        else                g = Wlo + (size_t)(nbase + row) * 256;
        g += kt * 32 + kc * 8;
        CP_ASYNC16(dst, g);
    }
}

__global__ void __launch_bounds__(256, 2) gemm_mma(int layer,
                                                   const float* __restrict__ b1v,
                                                   const float* __restrict__ b2v,
                                                   float* __restrict__ dout) {
    extern __shared__ char dsm[];
    int tid = threadIdx.x, lane = tid & 31, wid = tid >> 5;
    int row0 = blockIdx.x * 128;
    int by   = blockIdx.y;
    int nbase = by * 128;

    const __half* A   = (layer == 1) ? g_a : g_b;
    const __half* Whi = (layer == 1) ? g_w1hi : g_w2hi;
    const __half* Wlo = (layer == 1) ? g_w1lo : g_w2lo;

    uint32_t sb = smem_u32(dsm);
    int mrow = (wid >> 1) * 32;
    int ncol = (wid & 1) * 64;

    float acc[2][8][4];
#pragma unroll
    for (int mt = 0; mt < 2; ++mt)
#pragma unroll
        for (int j = 0; j < 8; ++j)
#pragma unroll
            for (int q = 0; q < 4; ++q) acc[mt][j][q] = 0.f;

    cp_stage(sb, A, Whi, Wlo, row0, nbase, 0, 0, tid);
    CP_COMMIT();

    for (int kt = 0; kt < 8; ++kt) {
        int st = kt & 1;
        CP_WAIT0();
        __syncthreads();
        if (kt < 7) {
            cp_stage(sb, A, Whi, Wlo, row0, nbase, kt + 1, st ^ 1, tid);
            CP_COMMIT();
        }
        const char* sa = dsm + st * STAGE_B;
#pragma unroll
        for (int ks = 0; ks < 2; ++ks) {
            uint32_t a_base = (uint32_t)((mrow + (lane >> 2)) * 80
                                         + (lane & 3) * 4 + ks * 32);
            uint32_t ah[2][4];
#pragma unroll
            for (int mt = 0; mt < 2; ++mt) {
                uint32_t o = a_base + mt * 1280;
                ah[mt][0] = *(const uint32_t*)(sa + o);
                ah[mt][1] = *(const uint32_t*)(sa + o + 640);
                ah[mt][2] = *(const uint32_t*)(sa + o + 16);
                ah[mt][3] = *(const uint32_t*)(sa + o + 656);
            }
            uint32_t b_base = (uint32_t)((ncol + (lane >> 2)) * 80
                                         + (lane & 3) * 4 + ks * 32);
#pragma unroll
            for (int j = 0; j < 8; ++j) {
                uint32_t o = b_base + j * 640;
                uint32_t bh0 = *(const uint32_t*)(sa + TILE_B + o);
                uint32_t bh1 = *(const uint32_t*)(sa + TILE_B + o + 16);
                uint32_t bl0 = *(const uint32_t*)(sa + 2 * TILE_B + o);
                uint32_t bl1 = *(const uint32_t*)(sa + 2 * TILE_B + o + 16);
#pragma unroll
                for (int mt = 0; mt < 2; ++mt) {
                    MMA_F16(acc[mt][j], ah[mt], bh0, bh1);
                    MMA_F16(acc[mt][j], ah[mt], bl0, bl1);
                }
            }
        }
        __syncthreads();
    }

    int r_base  = row0 + mrow + (lane >> 2);
    int cl_base = ncol + (lane & 3) * 2;
    if (layer == 1) {
        // h = relu(acc + b1) -> fp16 into g_b (layer2 input)
#pragma unroll
        for (int mt = 0; mt < 2; ++mt)
#pragma unroll
            for (int j = 0; j < 8; ++j) {
                int gn = nbase + cl_base + j * 8;
                float bx0 = b1v[gn], bx1 = b1v[gn + 1];
#pragma unroll
                for (int hh = 0; hh < 2; ++hh) {
                    int r = r_base + mt * 16 + hh * 8;
                    float v0 = fmaxf(acc[mt][j][hh * 2]     + bx0, 0.f);
                    float v1 = fmaxf(acc[mt][j][hh * 2 + 1] + bx1, 0.f);
                    __half hp[2] = {__float2half(v0), __float2half(v1)};
                    *(uint32_t*)(g_b + (size_t)r * 256 + gn) = *(const uint32_t*)hp;
                }
            }
    } else {
#pragma unroll
        for (int mt = 0; mt < 2; ++mt)
#pragma unroll
            for (int j = 0; j < 8; ++j) {
                int cl = cl_base + j * 8;
#pragma unroll
                for (int hh = 0; hh < 2; ++hh) {
                    int r = r_base + mt * 16 + hh * 8;
                    float v0 = acc[mt][j][hh * 2];
                    float v1 = acc[mt][j][hh * 2 + 1];
                    if (by == 0) {
                        __half hp[2] = {__float2half(v0), __float2half(v1)};
                        *(uint32_t*)(g_p + (size_t)r * 128 + cl) = *(const uint32_t*)hp;
                    } else if (r < NNODES) {
                        float2 w = make_float2(v0 + b2v[cl], v1 + b2v[cl + 1]);
                        *(float2*)(dout + (size_t)r * 128 + cl) = w;
                    }
                }
            }
    }
}

extern "C" void kernel_launch(void* const* d_in, const int* in_sizes, int n_in,
                              void* d_out, int out_size) {
    const float* x   = (const float*)d_in[0];
    const void*  ei  = d_in[1];
    const float* W1l = (const float*)d_in[2];
    const float* b1  = (const float*)d_in[3];
    const float* W1r = (const float*)d_in[4];
    const float* W2l = (const float*)d_in[5];
    const float* b2  = (const float*)d_in[6];
    const float* W2r = (const float*)d_in[7];
    float* out = (float*)d_out;

    cudaFuncSetAttribute(gemm_mma, cudaFuncAttributeMaxDynamicSharedMemorySize,
                         GEMM_SMEM);

    // CSR build (once) + weight prep + x fp16 convert
    detect_kernel<<<1, 256>>>((const int*)ei);
    zero_wix<<<(NNODES + 255) / 256, 256>>>();
    count_kernel<<<(NEDGES + 255) / 256, 256>>>(ei);
    xconv_kernel<<<12500, 256>>>(x);
    blocksum_kernel<<<SCAN_BLOCKS, 1024>>>();
    scan_bsum<<<1, 128>>>();
    rowptr_kernel<<<SCAN_BLOCKS, 1024>>>();
    scatter_kernel<<<(NEDGES + 255) / 256, 256>>>(ei);
    prep_weights<<<256, 256>>>(W1l, W1r, W2l, W2r);
    pad_kernel<<<NPAD - NNODES, 64>>>();

    // layer 1: gather-mean(x fp16)+xsplit -> g_a, then GEMM -> g_b
    gather_kernel<<<12500, 256>>>(out, 0);
    gemm_mma<<<dim3(NBM, 2), 256, GEMM_SMEM>>>(1, b1, b2, out);

    // layer 2: GEMM (p fp16 -> g_p, r + b2 -> out), then out += gather-mean(p)
    gemm_mma<<<dim3(NBM, 2), 256, GEMM_SMEM>>>(2, b1, b2, out);
    gather_kernel<<<12500, 256>>>(out, 1);
}

// round 13
// speedup vs baseline: 1.0786x; 1.0786x over previous
#include <cuda_runtime.h>
#include <cuda_fp16.h>
#include <cstdint>
#include <cstddef>

#define NNODES 100000
#define NPAD   100096           // 782 * 128
#define NEDGES 1600000
#define NBM    782              // NPAD / 128
#define SCAN_BLOCKS 98          // 98 * 1024 >= NNODES

// ---------------- scratch (device globals) ----------------
__device__ __align__(16) __half g_p  [(size_t)NPAD * 128];   // h @ W2l^T in fp16
__device__ __align__(16) __half g_xh [(size_t)NNODES * 128]; // x in fp16
__device__ __align__(16) __half g_a  [(size_t)NPAD * 256];   // layer1 input fp16
__device__ __align__(16) __half g_b  [(size_t)NPAD * 256];   // layer2 input fp16
__device__ __align__(16) __half g_w1hi[256 * 256];
__device__ __align__(16) __half g_w1lo[256 * 256];
__device__ __align__(16) __half g_w2hi[256 * 256];
__device__ __align__(16) __half g_w2lo[256 * 256];
__device__ int g_rowptr[NNODES + 1];
__device__ int g_wix[NNODES];
__device__ int g_srcidx[NEDGES];
__device__ int g_bsum[SCAN_BLOCKS];
__device__ int g_boff[SCAN_BLOCKS];
__device__ int g_is64;

__device__ __forceinline__ uint32_t smem_u32(const void* p) {
    uint32_t a;
    asm("{ .reg .u64 t; cvta.to.shared.u64 t, %1; cvt.u32.u64 %0, t; }"
        : "=r"(a) : "l"(p));
    return a;
}

#define MMA_F16(c, a, b0, b1) \
    asm volatile("mma.sync.aligned.m16n8k16.row.col.f32.f16.f16.f32 " \
        "{%0,%1,%2,%3}, {%4,%5,%6,%7}, {%8,%9}, {%0,%1,%2,%3};" \
        : "+f"((c)[0]), "+f"((c)[1]), "+f"((c)[2]), "+f"((c)[3]) \
        : "r"((a)[0]), "r"((a)[1]), "r"((a)[2]), "r"((a)[3]), "r"(b0), "r"(b1))

#define CP_ASYNC16(dst, src) \
    asm volatile("cp.async.cg.shared.global [%0], [%1], 16;" \
                 :: "r"(dst), "l"(src) : "memory")
#define CP_COMMIT() asm volatile("cp.async.commit_group;" ::: "memory")
#define CP_WAIT0()  asm volatile("cp.async.wait_group 0;" ::: "memory")

// ---------------- edge index decode ----------------
__device__ __forceinline__ void load_edge(const void* ei, int e, int& s, int& t) {
    if (g_is64) {
        const long long* e64 = (const long long*)ei;
        s = (int)e64[e];
        t = (int)e64[(size_t)NEDGES + e];
    } else {
        const int* e32 = (const int*)ei;
        s = e32[e];
        t = e32[(size_t)NEDGES + e];
    }
}

// block 0: dtype detect; blocks 1..: zero g_wix
__global__ void detect_zero_kernel(const int* __restrict__ ei32) {
    if (blockIdx.x == 0) {
        __shared__ int sOr;
        if (threadIdx.x == 0) sOr = 0;
        __syncthreads();
        int acc = 0;
        for (int i = threadIdx.x; i < 2048; i += blockDim.x) acc |= ei32[2 * i + 1];
        atomicOr(&sOr, acc);
        __syncthreads();
        if (threadIdx.x == 0) g_is64 = (sOr == 0) ? 1 : 0;
    } else {
        int i = (blockIdx.x - 1) * 256 + threadIdx.x;
        if (i < NNODES) g_wix[i] = 0;
    }
}

__global__ void count_kernel(const void* __restrict__ ei) {
    int e = blockIdx.x * blockDim.x + threadIdx.x;
    if (e >= NEDGES) return;
    int s, t;
    load_edge(ei, e, s, t);
    if ((unsigned)s >= NNODES || (unsigned)t >= NNODES) return;
    atomicAdd(&g_wix[t], 1);
}

__global__ void blocksum_kernel() {
    __shared__ int red[32];
    int idx = blockIdx.x * 1024 + threadIdx.x;
    int v = (idx < NNODES) ? g_wix[idx] : 0;
#pragma unroll
    for (int o = 16; o > 0; o >>= 1) v += __shfl_down_sync(0xFFFFFFFFu, v, o);
    if ((threadIdx.x & 31) == 0) red[threadIdx.x >> 5] = v;
    __syncthreads();
    if (threadIdx.x < 32) {
        int w = red[threadIdx.x];
#pragma unroll
        for (int o = 16; o > 0; o >>= 1) w += __shfl_down_sync(0xFFFFFFFFu, w, o);
        if (threadIdx.x == 0) g_bsum[blockIdx.x] = w;
    }
}

__global__ void scan_bsum() {
    __shared__ int s[SCAN_BLOCKS];
    int tid = threadIdx.x;
    if (tid < SCAN_BLOCKS) s[tid] = g_bsum[tid];
    __syncthreads();
    if (tid == 0) {
        int run = 0;
        for (int i = 0; i < SCAN_BLOCKS; ++i) {
            g_boff[i] = run;
            run += s[i];
        }
        g_rowptr[NNODES] = run;
    }
}

__global__ void rowptr_kernel() {
    __shared__ int sc[1024];
    int tid = threadIdx.x;
    int idx = blockIdx.x * 1024 + tid;
    int v = (idx < NNODES) ? g_wix[idx] : 0;
    sc[tid] = v;
    __syncthreads();
#pragma unroll
    for (int off = 1; off < 1024; off <<= 1) {
        int u = (tid >= off) ? sc[tid - off] : 0;
        __syncthreads();
        sc[tid] += u;
        __syncthreads();
    }
    if (idx < NNODES) {
        int excl = sc[tid] - v + g_boff[blockIdx.x];
        g_rowptr[idx] = excl;
        g_wix[idx] = excl;
    }
}

__global__ void scatter_kernel(const void* __restrict__ ei) {
    int e = blockIdx.x * blockDim.x + threadIdx.x;
    if (e >= NEDGES) return;
    int s, t;
    load_edge(ei, e, s, t);
    if ((unsigned)s >= NNODES || (unsigned)t >= NNODES) return;
    int pos = atomicAdd(&g_wix[t], 1);
    g_srcidx[pos] = s;
}

// ---------------- x -> fp16 convert (+ pad-row zeroing in extra blocks) ----------------
__global__ void xconv_kernel(const float* __restrict__ x) {
    if (blockIdx.x >= 12500) {                 // 96 pad blocks
        int r = NNODES + (blockIdx.x - 12500);
        int q = threadIdx.x;                    // 256 threads? use first 64
        if (q < 64) {
            uint2 z = make_uint2(0u, 0u);
            *(uint2*)(g_a + (size_t)r * 256 + q * 4) = z;
        }
        return;
    }
    int idx = blockIdx.x * 256 + threadIdx.x;   // float4 index, NNODES*32 total
    if (idx >= NNODES * 32) return;
    float4 v = ((const float4*)x)[idx];
    __half hm[4] = {__float2half(v.x), __float2half(v.y),
                    __float2half(v.z), __float2half(v.w)};
    *(uint2*)(g_xh + (size_t)idx * 4) = *(const uint2*)hm;
}

// ---------------- gather aggregation: one warp per node, fp16 rows (R11 form) ----------------
// phase 0: mean of g_xh rows -> fp16 cols [0,128); g_xh[node] -> cols [128,256)
// phase 1: mean of g_p rows -> out[node] += mean
__global__ void gather_kernel(float* __restrict__ out, int phase) {
    int node = (int)(((size_t)blockIdx.x * blockDim.x + threadIdx.x) >> 5);
    int lane = threadIdx.x & 31;
    if (node >= NNODES) return;
    int beg = g_rowptr[node];
    int end = g_rowptr[node + 1];
    const __half* src = (phase == 0) ? g_xh : g_p;

    float a0 = 0.f, a1 = 0.f, a2 = 0.f, a3 = 0.f;
    int i = beg;
    for (; i + 7 < end; i += 8) {
        int sx[8];
#pragma unroll
        for (int u = 0; u < 8; ++u) sx[u] = g_srcidx[i + u];
        uint2 v[8];
#pragma unroll
        for (int u = 0; u < 8; ++u)
            v[u] = *(const uint2*)(src + ((size_t)sx[u] << 7) + lane * 4);
#pragma unroll
        for (int u = 0; u < 8; ++u) {
            float2 f0 = __half22float2(*(const __half2*)&v[u].x);
            float2 f1 = __half22float2(*(const __half2*)&v[u].y);
            a0 += f0.x; a1 += f0.y; a2 += f1.x; a3 += f1.y;
        }
    }
    if (i + 3 < end) {
        int sx[4];
#pragma unroll
        for (int u = 0; u < 4; ++u) sx[u] = g_srcidx[i + u];
        uint2 v[4];
#pragma unroll
        for (int u = 0; u < 4; ++u)
            v[u] = *(const uint2*)(src + ((size_t)sx[u] << 7) + lane * 4);
#pragma unroll
        for (int u = 0; u < 4; ++u) {
            float2 f0 = __half22float2(*(const __half2*)&v[u].x);
            float2 f1 = __half22float2(*(const __half2*)&v[u].y);
            a0 += f0.x; a1 += f0.y; a2 += f1.x; a3 += f1.y;
        }
        i += 4;
    }
    for (; i < end; ++i) {
        uint2 v0 = *(const uint2*)(src + ((size_t)g_srcidx[i] << 7) + lane * 4);
        float2 f0 = __half22float2(*(const __half2*)&v0.x);
        float2 f1 = __half22float2(*(const __half2*)&v0.y);
        a0 += f0.x; a1 += f0.y; a2 += f1.x; a3 += f1.y;
    }
    float rdeg = 1.0f / fmaxf((float)(end - beg), 1.0f);

    if (phase == 0) {
        __half hm[4] = {__float2half(a0 * rdeg), __float2half(a1 * rdeg),
                        __float2half(a2 * rdeg), __float2half(a3 * rdeg)};
        *(uint2*)(g_a + (size_t)node * 256 + lane * 4) = *(const uint2*)hm;
        // fused xsplit: copy x[node] fp16 -> cols [128,256)
        uint2 xr = *(const uint2*)(g_xh + ((size_t)node << 7) + lane * 4);
        *(uint2*)(g_a + (size_t)node * 256 + 128 + lane * 4) = xr;
    } else {
        float4* op = (float4*)out + (size_t)node * 32 + lane;
        float4 o = *op;
        o.x += a0 * rdeg; o.y += a1 * rdeg;
        o.z += a2 * rdeg; o.w += a3 * rdeg;
        *op = o;
    }
}

__global__ void prep_weights(const float* __restrict__ W1l, const float* __restrict__ W1r,
                             const float* __restrict__ W2l, const float* __restrict__ W2r) {
    int j = blockIdx.x;    // out dim
    int k = threadIdx.x;   // in dim
    float w1 = (k < 128) ? W1l[j * 128 + k] : W1r[j * 128 + (k - 128)];
    float w2 = (j < 128) ? W2l[j * 256 + k] : W2r[(j - 128) * 256 + k];
    __half h1 = __float2half(w1);
    __half h2 = __float2half(w2);
    g_w1hi[j * 256 + k] = h1;
    g_w1lo[j * 256 + k] = __float2half(w1 - __half2float(h1));
    g_w2hi[j * 256 + k] = h2;
    g_w2lo[j * 256 + k] = __float2half(w2 - __half2float(h2));
}

// ---------------- mma.sync GEMM: 2-term fp16 (A single, W hi/lo) ----------------
#define TILE_B   10240      // 128 * 80
#define STAGE_B  30720
#define GEMM_SMEM 61440

__device__ __forceinline__ void cp_stage(uint32_t sb,
    const __half* A, const __half* Whi, const __half* Wlo,
    int row0, int nbase, int kt, int st, int tid) {
#pragma unroll
    for (int i = 0; i < 6; ++i) {
        int c = i * 256 + tid;          // 0..1535
        int tile = c >> 9;              // 0:A 1:Whi 2:Wlo
        int idx  = c & 511;
        int row  = idx >> 2;
        int kc   = idx & 3;
        uint32_t dst = sb + st * STAGE_B + tile * TILE_B
                     + (uint32_t)(row * 80 + kc * 16);
        const __half* g;
        if (tile == 0)      g = A   + (size_t)(row0 + row) * 256;
        else if (tile == 1) g = Whi + (size_t)(nbase + row) * 256;
        else                g = Wlo + (size_t)(nbase + row) * 256;
        g += kt * 32 + kc * 8;
        CP_ASYNC16(dst, g);
    }
}

__global__ void __launch_bounds__(256, 2) gemm_mma(int layer,
                                                   const float* __restrict__ b1v,
                                                   const float* __restrict__ b2v,
                                                   float* __restrict__ dout) {
    extern __shared__ char dsm[];
    int tid = threadIdx.x, lane = tid & 31, wid = tid >> 5;
    int row0 = blockIdx.x * 128;
    int by   = blockIdx.y;
    int nbase = by * 128;

    const __half* A   = (layer == 1) ? g_a : g_b;
    const __half* Whi = (layer == 1) ? g_w1hi : g_w2hi;
    const __half* Wlo = (layer == 1) ? g_w1lo : g_w2lo;

    uint32_t sb = smem_u32(dsm);
    int mrow = (wid >> 1) * 32;
    int ncol = (wid & 1) * 64;

    float acc[2][8][4];
#pragma unroll
    for (int mt = 0; mt < 2; ++mt)
#pragma unroll
        for (int j = 0; j < 8; ++j)
#pragma unroll
            for (int q = 0; q < 4; ++q) acc[mt][j][q] = 0.f;

    cp_stage(sb, A, Whi, Wlo, row0, nbase, 0, 0, tid);
    CP_COMMIT();

    for (int kt = 0; kt < 8; ++kt) {
        int st = kt & 1;
        CP_WAIT0();
        __syncthreads();
        if (kt < 7) {
            cp_stage(sb, A, Whi, Wlo, row0, nbase, kt + 1, st ^ 1, tid);
            CP_COMMIT();
        }
        const char* sa = dsm + st * STAGE_B;
#pragma unroll
        for (int ks = 0; ks < 2; ++ks) {
            uint32_t a_base = (uint32_t)((mrow + (lane >> 2)) * 80
                                         + (lane & 3) * 4 + ks * 32);
            uint32_t ah[2][4];
#pragma unroll
            for (int mt = 0; mt < 2; ++mt) {
                uint32_t o = a_base + mt * 1280;
                ah[mt][0] = *(const uint32_t*)(sa + o);
                ah[mt][1] = *(const uint32_t*)(sa + o + 640);
                ah[mt][2] = *(const uint32_t*)(sa + o + 16);
                ah[mt][3] = *(const uint32_t*)(sa + o + 656);
            }
            uint32_t b_base = (uint32_t)((ncol + (lane >> 2)) * 80
                                         + (lane & 3) * 4 + ks * 32);
#pragma unroll
            for (int j = 0; j < 8; ++j) {
                uint32_t o = b_base + j * 640;
                uint32_t bh0 = *(const uint32_t*)(sa + TILE_B + o);
                uint32_t bh1 = *(const uint32_t*)(sa + TILE_B + o + 16);
                uint32_t bl0 = *(const uint32_t*)(sa + 2 * TILE_B + o);
                uint32_t bl1 = *(const uint32_t*)(sa + 2 * TILE_B + o + 16);
#pragma unroll
                for (int mt = 0; mt < 2; ++mt) {
                    MMA_F16(acc[mt][j], ah[mt], bh0, bh1);
                    MMA_F16(acc[mt][j], ah[mt], bl0, bl1);
                }
            }
        }
        __syncthreads();
    }

    int r_base  = row0 + mrow + (lane >> 2);
    int cl_base = ncol + (lane & 3) * 2;
    if (layer == 1) {
        // h = relu(acc + b1) -> fp16 into g_b (layer2 input)
#pragma unroll
        for (int mt = 0; mt < 2; ++mt)
#pragma unroll
            for (int j = 0; j < 8; ++j) {
                int gn = nbase + cl_base + j * 8;
                float bx0 = b1v[gn], bx1 = b1v[gn + 1];
#pragma unroll
                for (int hh = 0; hh < 2; ++hh) {
                    int r = r_base + mt * 16 + hh * 8;
                    float v0 = fmaxf(acc[mt][j][hh * 2]     + bx0, 0.f);
                    float v1 = fmaxf(acc[mt][j][hh * 2 + 1] + bx1, 0.f);
                    __half hp[2] = {__float2half(v0), __float2half(v1)};
                    *(uint32_t*)(g_b + (size_t)r * 256 + gn) = *(const uint32_t*)hp;
                }
            }
    } else {
#pragma unroll
        for (int mt = 0; mt < 2; ++mt)
#pragma unroll
            for (int j = 0; j < 8; ++j) {
                int cl = cl_base + j * 8;
#pragma unroll
                for (int hh = 0; hh < 2; ++hh) {
                    int r = r_base + mt * 16 + hh * 8;
                    float v0 = acc[mt][j][hh * 2];
                    float v1 = acc[mt][j][hh * 2 + 1];
                    if (by == 0) {
                        __half hp[2] = {__float2half(v0), __float2half(v1)};
                        *(uint32_t*)(g_p + (size_t)r * 128 + cl) = *(const uint32_t*)hp;
                    } else if (r < NNODES) {
                        float2 w = make_float2(v0 + b2v[cl], v1 + b2v[cl + 1]);
                        *(float2*)(dout + (size_t)r * 128 + cl) = w;
                    }
                }
            }
    }
}

extern "C" void kernel_launch(void* const* d_in, const int* in_sizes, int n_in,
                              void* d_out, int out_size) {
    const float* x   = (const float*)d_in[0];
    const void*  ei  = d_in[1];
    const float* W1l = (const float*)d_in[2];
    const float* b1  = (const float*)d_in[3];
    const float* W1r = (const float*)d_in[4];
    const float* W2l = (const float*)d_in[5];
    const float* b2  = (const float*)d_in[6];
    const float* W2r = (const float*)d_in[7];
    float* out = (float*)d_out;

    cudaFuncSetAttribute(gemm_mma, cudaFuncAttributeMaxDynamicSharedMemorySize,
                         GEMM_SMEM);

    // CSR build (once) + weight prep + x fp16 convert (+ pad rows)
    detect_zero_kernel<<<1 + (NNODES + 255) / 256, 256>>>((const int*)ei);
    count_kernel<<<(NEDGES + 255) / 256, 256>>>(ei);
    xconv_kernel<<<12500 + (NPAD - NNODES), 256>>>(x);
    blocksum_kernel<<<SCAN_BLOCKS, 1024>>>();
    scan_bsum<<<1, 128>>>();
    rowptr_kernel<<<SCAN_BLOCKS, 1024>>>();
    scatter_kernel<<<(NEDGES + 255) / 256, 256>>>(ei);
    prep_weights<<<256, 256>>>(W1l, W1r, W2l, W2r);

    // layer 1: gather-mean(x fp16)+xsplit -> g_a, then GEMM -> g_b
    gather_kernel<<<12500, 256>>>(out, 0);
    gemm_mma<<<dim3(NBM, 2), 256, GEMM_SMEM>>>(1, b1, b2, out);

    // layer 2: GEMM (p fp16 -> g_p, r + b2 -> out), then out += gather-mean(p)
    gemm_mma<<<dim3(NBM, 2), 256, GEMM_SMEM>>>(2, b1, b2, out);
    gather_kernel<<<12500, 256>>>(out, 1);
}

// round 14
// speedup vs baseline: 1.3077x; 1.2124x over previous
#include <cuda_runtime.h>
#include <cuda_fp16.h>
#include <cstdint>
#include <cstddef>

#define NNODES 100000
#define NPAD   100096           // 782 * 128
#define NEDGES 1600000
#define NBM    782              // NPAD / 128
#define SCAN_BLOCKS 98          // 98 * 1024 >= NNODES

// ---------------- scratch (device globals) ----------------
__device__ __align__(16) __half g_p  [(size_t)NPAD * 128];   // h @ W2l^T in fp16
__device__ __align__(16) __half g_xh [(size_t)NNODES * 128]; // x in fp16
__device__ __align__(16) __half g_a  [(size_t)NPAD * 256];   // layer1 input fp16
__device__ __align__(16) __half g_b  [(size_t)NPAD * 256];   // layer2 input fp16
__device__ __align__(16) __half g_w1 [256 * 256];
__device__ __align__(16) __half g_w2 [256 * 256];
__device__ int g_rowptr[NNODES + 1];
__device__ int g_wix[NNODES];
__device__ int g_srcidx[NEDGES];
__device__ int g_bsum[SCAN_BLOCKS];
__device__ int g_boff[SCAN_BLOCKS];
__device__ int g_is64;

__device__ __forceinline__ uint32_t smem_u32(const void* p) {
    uint32_t a;
    asm("{ .reg .u64 t; cvta.to.shared.u64 t, %1; cvt.u32.u64 %0, t; }"
        : "=r"(a) : "l"(p));
    return a;
}

#define MMA_F16(c, a, b0, b1) \
    asm volatile("mma.sync.aligned.m16n8k16.row.col.f32.f16.f16.f32 " \
        "{%0,%1,%2,%3}, {%4,%5,%6,%7}, {%8,%9}, {%0,%1,%2,%3};" \
        : "+f"((c)[0]), "+f"((c)[1]), "+f"((c)[2]), "+f"((c)[3]) \
        : "r"((a)[0]), "r"((a)[1]), "r"((a)[2]), "r"((a)[3]), "r"(b0), "r"(b1))

#define CP_ASYNC16(dst, src) \
    asm volatile("cp.async.cg.shared.global [%0], [%1], 16;" \
                 :: "r"(dst), "l"(src) : "memory")
#define CP_COMMIT() asm volatile("cp.async.commit_group;" ::: "memory")
#define CP_WAIT0()  asm volatile("cp.async.wait_group 0;" ::: "memory")

// ---------------- edge index decode ----------------
__device__ __forceinline__ void load_edge(const void* ei, int e, int& s, int& t) {
    if (g_is64) {
        const long long* e64 = (const long long*)ei;
        s = (int)e64[e];
        t = (int)e64[(size_t)NEDGES + e];
    } else {
        const int* e32 = (const int*)ei;
        s = e32[e];
        t = e32[(size_t)NEDGES + e];
    }
}

// block 0: dtype detect; blocks 1..: zero g_wix
__global__ void detect_zero_kernel(const int* __restrict__ ei32) {
    if (blockIdx.x == 0) {
        __shared__ int sOr;
        if (threadIdx.x == 0) sOr = 0;
        __syncthreads();
        int acc = 0;
        for (int i = threadIdx.x; i < 2048; i += blockDim.x) acc |= ei32[2 * i + 1];
        atomicOr(&sOr, acc);
        __syncthreads();
        if (threadIdx.x == 0) g_is64 = (sOr == 0) ? 1 : 0;
    } else {
        int i = (blockIdx.x - 1) * 256 + threadIdx.x;
        if (i < NNODES) g_wix[i] = 0;
    }
}

__global__ void count_kernel(const void* __restrict__ ei) {
    int e = blockIdx.x * blockDim.x + threadIdx.x;
    if (e >= NEDGES) return;
    int s, t;
    load_edge(ei, e, s, t);
    if ((unsigned)s >= NNODES || (unsigned)t >= NNODES) return;
    atomicAdd(&g_wix[t], 1);
}

__global__ void blocksum_kernel() {
    __shared__ int red[32];
    int idx = blockIdx.x * 1024 + threadIdx.x;
    int v = (idx < NNODES) ? g_wix[idx] : 0;
#pragma unroll
    for (int o = 16; o > 0; o >>= 1) v += __shfl_down_sync(0xFFFFFFFFu, v, o);
    if ((threadIdx.x & 31) == 0) red[threadIdx.x >> 5] = v;
    __syncthreads();
    if (threadIdx.x < 32) {
        int w = red[threadIdx.x];
#pragma unroll
        for (int o = 16; o > 0; o >>= 1) w += __shfl_down_sync(0xFFFFFFFFu, w, o);
        if (threadIdx.x == 0) g_bsum[blockIdx.x] = w;
    }
}

__global__ void scan_bsum() {
    __shared__ int s[SCAN_BLOCKS];
    int tid = threadIdx.x;
    if (tid < SCAN_BLOCKS) s[tid] = g_bsum[tid];
    __syncthreads();
    if (tid == 0) {
        int run = 0;
        for (int i = 0; i < SCAN_BLOCKS; ++i) {
            g_boff[i] = run;
            run += s[i];
        }
        g_rowptr[NNODES] = run;
    }
}

__global__ void rowptr_kernel() {
    __shared__ int sc[1024];
    int tid = threadIdx.x;
    int idx = blockIdx.x * 1024 + tid;
    int v = (idx < NNODES) ? g_wix[idx] : 0;
    sc[tid] = v;
    __syncthreads();
#pragma unroll
    for (int off = 1; off < 1024; off <<= 1) {
        int u = (tid >= off) ? sc[tid - off] : 0;
        __syncthreads();
        sc[tid] += u;
        __syncthreads();
    }
    if (idx < NNODES) {
        int excl = sc[tid] - v + g_boff[blockIdx.x];
        g_rowptr[idx] = excl;
        g_wix[idx] = excl;
    }
}

__global__ void scatter_kernel(const void* __restrict__ ei) {
    int e = blockIdx.x * blockDim.x + threadIdx.x;
    if (e >= NEDGES) return;
    int s, t;
    load_edge(ei, e, s, t);
    if ((unsigned)s >= NNODES || (unsigned)t >= NNODES) return;
    int pos = atomicAdd(&g_wix[t], 1);
    g_srcidx[pos] = s;
}

// ---------------- x -> fp16 convert (+ pad-row zeroing in extra blocks) ----------------
__global__ void xconv_kernel(const float* __restrict__ x) {
    if (blockIdx.x >= 12500) {                 // 96 pad blocks
        int r = NNODES + (blockIdx.x - 12500);
        int q = threadIdx.x;
        if (q < 64) {
            uint2 z = make_uint2(0u, 0u);
            *(uint2*)(g_a + (size_t)r * 256 + q * 4) = z;
        }
        return;
    }
    int idx = blockIdx.x * 256 + threadIdx.x;   // float4 index, NNODES*32 total
    if (idx >= NNODES * 32) return;
    float4 v = ((const float4*)x)[idx];
    __half hm[4] = {__float2half(v.x), __float2half(v.y),
                    __float2half(v.z), __float2half(v.w)};
    *(uint2*)(g_xh + (size_t)idx * 4) = *(const uint2*)hm;
}

// ---------------- gather aggregation: one warp per node, fp16 rows ----------------
// phase 0: mean of g_xh rows -> fp16 cols [0,128); g_xh[node] -> cols [128,256)
// phase 1: mean of g_p rows -> out[node] += mean
__global__ void gather_kernel(float* __restrict__ out, int phase) {
    int node = (int)(((size_t)blockIdx.x * blockDim.x + threadIdx.x) >> 5);
    int lane = threadIdx.x & 31;
    if (node >= NNODES) return;
    int beg = g_rowptr[node];
    int end = g_rowptr[node + 1];
    const __half* src = (phase == 0) ? g_xh : g_p;

    float a0 = 0.f, a1 = 0.f, a2 = 0.f, a3 = 0.f;
    int i = beg;
    for (; i + 7 < end; i += 8) {
        int sx[8];
#pragma unroll
        for (int u = 0; u < 8; ++u) sx[u] = g_srcidx[i + u];
        uint2 v[8];
#pragma unroll
        for (int u = 0; u < 8; ++u)
            v[u] = *(const uint2*)(src + ((size_t)sx[u] << 7) + lane * 4);
#pragma unroll
        for (int u = 0; u < 8; ++u) {
            float2 f0 = __half22float2(*(const __half2*)&v[u].x);
            float2 f1 = __half22float2(*(const __half2*)&v[u].y);
            a0 += f0.x; a1 += f0.y; a2 += f1.x; a3 += f1.y;
        }
    }
    if (i + 3 < end) {
        int sx[4];
#pragma unroll
        for (int u = 0; u < 4; ++u) sx[u] = g_srcidx[i + u];
        uint2 v[4];
#pragma unroll
        for (int u = 0; u < 4; ++u)
            v[u] = *(const uint2*)(src + ((size_t)sx[u] << 7) + lane * 4);
#pragma unroll
        for (int u = 0; u < 4; ++u) {
            float2 f0 = __half22float2(*(const __half2*)&v[u].x);
            float2 f1 = __half22float2(*(const __half2*)&v[u].y);
            a0 += f0.x; a1 += f0.y; a2 += f1.x; a3 += f1.y;
        }
        i += 4;
    }
    for (; i < end; ++i) {
        uint2 v0 = *(const uint2*)(src + ((size_t)g_srcidx[i] << 7) + lane * 4);
        float2 f0 = __half22float2(*(const __half2*)&v0.x);
        float2 f1 = __half22float2(*(const __half2*)&v0.y);
        a0 += f0.x; a1 += f0.y; a2 += f1.x; a3 += f1.y;
    }
    float rdeg = 1.0f / fmaxf((float)(end - beg), 1.0f);

    if (phase == 0) {
        __half hm[4] = {__float2half(a0 * rdeg), __float2half(a1 * rdeg),
                        __float2half(a2 * rdeg), __float2half(a3 * rdeg)};
        *(uint2*)(g_a + (size_t)node * 256 + lane * 4) = *(const uint2*)hm;
        // fused xsplit: copy x[node] fp16 -> cols [128,256)
        uint2 xr = *(const uint2*)(g_xh + ((size_t)node << 7) + lane * 4);
        *(uint2*)(g_a + (size_t)node * 256 + 128 + lane * 4) = xr;
    } else {
        float4* op = (float4*)out + (size_t)node * 32 + lane;
        float4 o = *op;
        o.x += a0 * rdeg; o.y += a1 * rdeg;
        o.z += a2 * rdeg; o.w += a3 * rdeg;
        *op = o;
    }
}

__global__ void prep_weights(const float* __restrict__ W1l, const float* __restrict__ W1r,
                             const float* __restrict__ W2l, const float* __restrict__ W2r) {
    int j = blockIdx.x;    // out dim
    int k = threadIdx.x;   // in dim
    float w1 = (k < 128) ? W1l[j * 128 + k] : W1r[j * 128 + (k - 128)];
    float w2 = (j < 128) ? W2l[j * 256 + k] : W2r[(j - 128) * 256 + k];
    g_w1[j * 256 + k] = __float2half(w1);
    g_w2[j * 256 + k] = __float2half(w2);
}

// ---------------- mma.sync GEMM: single-term fp16 ----------------
// SMEM stage (20480B): A, W tiles of 128 rows x 32 fp16, rows padded to 80B.
// Two stages, cp.async double buffering.
#define TILE_B   10240      // 128 * 80
#define STAGE_B  20480
#define GEMM_SMEM 40960

__device__ __forceinline__ void cp_stage(uint32_t sb,
    const __half* A, const __half* W,
    int row0, int nbase, int kt, int st, int tid) {
#pragma unroll
    for (int i = 0; i < 4; ++i) {
        int c = i * 256 + tid;          // 0..1023
        int tile = c >> 9;              // 0:A 1:W
        int idx  = c & 511;
        int row  = idx >> 2;
        int kc   = idx & 3;
        uint32_t dst = sb + st * STAGE_B + tile * TILE_B
                     + (uint32_t)(row * 80 + kc * 16);
        const __half* g = (tile == 0) ? (A + (size_t)(row0 + row) * 256)
                                      : (W + (size_t)(nbase + row) * 256);
        g += kt * 32 + kc * 8;
        CP_ASYNC16(dst, g);
    }
}

__global__ void __launch_bounds__(256, 2) gemm_mma(int layer,
                                                   const float* __restrict__ b1v,
                                                   const float* __restrict__ b2v,
                                                   float* __restrict__ dout) {
    extern __shared__ char dsm[];
    int tid = threadIdx.x, lane = tid & 31, wid = tid >> 5;
    int row0 = blockIdx.x * 128;
    int by   = blockIdx.y;
    int nbase = by * 128;

    const __half* A = (layer == 1) ? g_a : g_b;
    const __half* W = (layer == 1) ? g_w1 : g_w2;

    uint32_t sb = smem_u32(dsm);
    int mrow = (wid >> 1) * 32;
    int ncol = (wid & 1) * 64;

    float acc[2][8][4];
#pragma unroll
    for (int mt = 0; mt < 2; ++mt)
#pragma unroll
        for (int j = 0; j < 8; ++j)
#pragma unroll
            for (int q = 0; q < 4; ++q) acc[mt][j][q] = 0.f;

    cp_stage(sb, A, W, row0, nbase, 0, 0, tid);
    CP_COMMIT();

    for (int kt = 0; kt < 8; ++kt) {
        int st = kt & 1;
        CP_WAIT0();
        __syncthreads();
        if (kt < 7) {
            cp_stage(sb, A, W, row0, nbase, kt + 1, st ^ 1, tid);
            CP_COMMIT();
        }
        const char* sa = dsm + st * STAGE_B;
#pragma unroll
        for (int ks = 0; ks < 2; ++ks) {
            uint32_t a_base = (uint32_t)((mrow + (lane >> 2)) * 80
                                         + (lane & 3) * 4 + ks * 32);
            uint32_t ah[2][4];
#pragma unroll
            for (int mt = 0; mt < 2; ++mt) {
                uint32_t o = a_base + mt * 1280;
                ah[mt][0] = *(const uint32_t*)(sa + o);
                ah[mt][1] = *(const uint32_t*)(sa + o + 640);
                ah[mt][2] = *(const uint32_t*)(sa + o + 16);
                ah[mt][3] = *(const uint32_t*)(sa + o + 656);
            }
            uint32_t b_base = (uint32_t)((ncol + (lane >> 2)) * 80
                                         + (lane & 3) * 4 + ks * 32);
#pragma unroll
            for (int j = 0; j < 8; ++j) {
                uint32_t o = b_base + j * 640;
                uint32_t bh0 = *(const uint32_t*)(sa + TILE_B + o);
                uint32_t bh1 = *(const uint32_t*)(sa + TILE_B + o + 16);
#pragma unroll
                for (int mt = 0; mt < 2; ++mt)
                    MMA_F16(acc[mt][j], ah[mt], bh0, bh1);
            }
        }
        __syncthreads();
    }

    int r_base  = row0 + mrow + (lane >> 2);
    int cl_base = ncol + (lane & 3) * 2;
    if (layer == 1) {
        // h = relu(acc + b1) -> fp16 into g_b (layer2 input)
#pragma unroll
        for (int mt = 0; mt < 2; ++mt)
#pragma unroll
            for (int j = 0; j < 8; ++j) {
                int gn = nbase + cl_base + j * 8;
                float bx0 = b1v[gn], bx1 = b1v[gn + 1];
#pragma unroll
                for (int hh = 0; hh < 2; ++hh) {
                    int r = r_base + mt * 16 + hh * 8;
                    float v0 = fmaxf(acc[mt][j][hh * 2]     + bx0, 0.f);
                    float v1 = fmaxf(acc[mt][j][hh * 2 + 1] + bx1, 0.f);
                    __half hp[2] = {__float2half(v0), __float2half(v1)};
                    *(uint32_t*)(g_b + (size_t)r * 256 + gn) = *(const uint32_t*)hp;
                }
            }
    } else {
#pragma unroll
        for (int mt = 0; mt < 2; ++mt)
#pragma unroll
            for (int j = 0; j < 8; ++j) {
                int cl = cl_base + j * 8;
#pragma unroll
                for (int hh = 0; hh < 2; ++hh) {
                    int r = r_base + mt * 16 + hh * 8;
                    float v0 = acc[mt][j][hh * 2];
                    float v1 = acc[mt][j][hh * 2 + 1];
                    if (by == 0) {
                        __half hp[2] = {__float2half(v0), __float2half(v1)};
                        *(uint32_t*)(g_p + (size_t)r * 128 + cl) = *(const uint32_t*)hp;
                    } else if (r < NNODES) {
                        float2 w = make_float2(v0 + b2v[cl], v1 + b2v[cl + 1]);
                        *(float2*)(dout + (size_t)r * 128 + cl) = w;
                    }
                }
            }
    }
}

extern "C" void kernel_launch(void* const* d_in, const int* in_sizes, int n_in,
                              void* d_out, int out_size) {
    const float* x   = (const float*)d_in[0];
    const void*  ei  = d_in[1];
    const float* W1l = (const float*)d_in[2];
    const float* b1  = (const float*)d_in[3];
    const float* W1r = (const float*)d_in[4];
    const float* W2l = (const float*)d_in[5];
    const float* b2  = (const float*)d_in[6];
    const float* W2r = (const float*)d_in[7];
    float* out = (float*)d_out;

    cudaFuncSetAttribute(gemm_mma, cudaFuncAttributeMaxDynamicSharedMemorySize,
                         GEMM_SMEM);

    // CSR build (once) + weight prep + x fp16 convert (+ pad rows)
    detect_zero_kernel<<<1 + (NNODES + 255) / 256, 256>>>((const int*)ei);
    count_kernel<<<(NEDGES + 255) / 256, 256>>>(ei);
    xconv_kernel<<<12500 + (NPAD - NNODES), 256>>>(x);
    blocksum_kernel<<<SCAN_BLOCKS, 1024>>>();
    scan_bsum<<<1, 128>>>();
    rowptr_kernel<<<SCAN_BLOCKS, 1024>>>();
    scatter_kernel<<<(NEDGES + 255) / 256, 256>>>(ei);
    prep_weights<<<256, 256>>>(W1l, W1r, W2l, W2r);

    // layer 1: gather-mean(x fp16)+xsplit -> g_a, then GEMM -> g_b
    gather_kernel<<<12500, 256>>>(out, 0);
    gemm_mma<<<dim3(NBM, 2), 256, GEMM_SMEM>>>(1, b1, b2, out);

    // layer 2: GEMM (p fp16 -> g_p, r + b2 -> out), then out += gather-mean(p)
    gemm_mma<<<dim3(NBM, 2), 256, GEMM_SMEM>>>(2, b1, b2, out);
    gather_kernel<<<12500, 256>>>(out, 1);
}

// round 15
// speedup vs baseline: 1.3483x; 1.0310x over previous
#include <cuda_runtime.h>
#include <cuda_fp16.h>
#include <cstdint>
#include <cstddef>

#define NNODES 100000
#define NPAD   100096           // 782 * 128
#define NEDGES 1600000
#define NBM    782              // NPAD / 128
#define SCAN_BLOCKS 98          // 98 * 1024 >= NNODES

// ---------------- scratch (device globals) ----------------
__device__ __align__(16) __half g_p  [(size_t)NPAD * 128];   // h @ W2l^T in fp16
__device__ __align__(16) __half g_xh [(size_t)NNODES * 128]; // x in fp16
__device__ __align__(16) __half g_a  [(size_t)NPAD * 256];   // layer1 input fp16
__device__ __align__(16) __half g_b  [(size_t)NPAD * 256];   // layer2 input fp16
__device__ __align__(16) __half g_w1 [256 * 256];
__device__ __align__(16) __half g_w2 [256 * 256];
__device__ int g_rowptr[NNODES + 1];
__device__ int g_wix[NNODES];
__device__ int g_srcidx[NEDGES];
__device__ volatile int g_lb_agg [SCAN_BLOCKS];
__device__ volatile int g_lb_flag[SCAN_BLOCKS];
__device__ int g_is64;

__device__ __forceinline__ uint32_t smem_u32(const void* p) {
    uint32_t a;
    asm("{ .reg .u64 t; cvta.to.shared.u64 t, %1; cvt.u32.u64 %0, t; }"
        : "=r"(a) : "l"(p));
    return a;
}

#define MMA_F16(c, a, b0, b1) \
    asm volatile("mma.sync.aligned.m16n8k16.row.col.f32.f16.f16.f32 " \
        "{%0,%1,%2,%3}, {%4,%5,%6,%7}, {%8,%9}, {%0,%1,%2,%3};" \
        : "+f"((c)[0]), "+f"((c)[1]), "+f"((c)[2]), "+f"((c)[3]) \
        : "r"((a)[0]), "r"((a)[1]), "r"((a)[2]), "r"((a)[3]), "r"(b0), "r"(b1))

#define CP_ASYNC16(dst, src) \
    asm volatile("cp.async.cg.shared.global [%0], [%1], 16;" \
                 :: "r"(dst), "l"(src) : "memory")
#define CP_COMMIT() asm volatile("cp.async.commit_group;" ::: "memory")
#define CP_WAIT0()  asm volatile("cp.async.wait_group 0;" ::: "memory")

// ---------------- mega-prologue ----------------
// block 0            : edge dtype detect + lookback flag reset
// blocks 1..392      : zero g_wix
// blocks 393..12892  : xconv (x -> g_xh fp16)
// blocks 12893..12988: zero pad rows of g_a
// blocks 12989..13244: prep weights (fp16)
#define MEGA_XC0   393
#define MEGA_PAD0  12893
#define MEGA_PREP0 12989
#define MEGA_BLOCKS 13245

__global__ void mega_prologue(const int* __restrict__ ei32,
                              const float* __restrict__ x,
                              const float* __restrict__ W1l,
                              const float* __restrict__ W1r,
                              const float* __restrict__ W2l,
                              const float* __restrict__ W2r) {
    int b = blockIdx.x;
    if (b == 0) {
        __shared__ int sOr;
        if (threadIdx.x == 0) sOr = 0;
        __syncthreads();
        int acc = 0;
        for (int i = threadIdx.x; i < 2048; i += blockDim.x) acc |= ei32[2 * i + 1];
        atomicOr(&sOr, acc);
        __syncthreads();
        if (threadIdx.x == 0) g_is64 = (sOr == 0) ? 1 : 0;
        if (threadIdx.x < SCAN_BLOCKS) g_lb_flag[threadIdx.x] = 0;
        return;
    }
    if (b < MEGA_XC0) {                       // zero g_wix
        int i = (b - 1) * 256 + threadIdx.x;
        if (i < NNODES) g_wix[i] = 0;
        return;
    }
    if (b < MEGA_PAD0) {                      // xconv
        int idx = (b - MEGA_XC0) * 256 + threadIdx.x;
        if (idx >= NNODES * 32) return;
        float4 v = ((const float4*)x)[idx];
        __half hm[4] = {__float2half(v.x), __float2half(v.y),
                        __float2half(v.z), __float2half(v.w)};
        *(uint2*)(g_xh + (size_t)idx * 4) = *(const uint2*)hm;
        return;
    }
    if (b < MEGA_PREP0) {                     // pad rows of g_a
        int r = NNODES + (b - MEGA_PAD0);
        if (threadIdx.x < 64) {
            uint2 z = make_uint2(0u, 0u);
            *(uint2*)(g_a + (size_t)r * 256 + threadIdx.x * 4) = z;
        }
        return;
    }
    {                                         // prep weights
        int j = b - MEGA_PREP0;               // out dim 0..255
        int k = threadIdx.x;                  // in dim 0..255
        float w1 = (k < 128) ? W1l[j * 128 + k] : W1r[j * 128 + (k - 128)];
        float w2 = (j < 128) ? W2l[j * 256 + k] : W2r[(j - 128) * 256 + k];
        g_w1[j * 256 + k] = __float2half(w1);
        g_w2[j * 256 + k] = __float2half(w2);
    }
}

// ---------------- count: read only target indices ----------------
__global__ void count_kernel(const void* __restrict__ ei) {
    int e = blockIdx.x * blockDim.x + threadIdx.x;
    if (e >= NEDGES) return;
    int t;
    if (g_is64) t = (int)((const long long*)ei)[(size_t)NEDGES + e];
    else        t = ((const int*)ei)[(size_t)NEDGES + e];
    if ((unsigned)t >= NNODES) return;
    atomicAdd(&g_wix[t], 1);
}

// ---------------- single-kernel decoupled-lookback scan ----------------
__global__ void scan_lb() {
    __shared__ int sc[1024];
    __shared__ int sv[128];
    int tid = threadIdx.x;
    int bid = blockIdx.x;
    int idx = bid * 1024 + tid;
    int v = (idx < NNODES) ? g_wix[idx] : 0;
    sc[tid] = v;
    __syncthreads();
#pragma unroll
    for (int off = 1; off < 1024; off <<= 1) {
        int u = (tid >= off) ? sc[tid - off] : 0;
        __syncthreads();
        sc[tid] += u;
        __syncthreads();
    }
    int total = sc[1023];
    if (tid == 0) {
        g_lb_agg[bid] = total;
        __threadfence();
        g_lb_flag[bid] = 1;
    }
    // gather predecessor aggregates in parallel
    if (tid < 128) sv[tid] = 0;
    __syncthreads();
    if (tid < bid) {
        while (g_lb_flag[tid] == 0) { }
        sv[tid] = g_lb_agg[tid];
    }
    __syncthreads();
#pragma unroll
    for (int off = 64; off > 0; off >>= 1) {
        if (tid < off) sv[tid] += sv[tid + off];
        __syncthreads();
    }
    int prefix = sv[0];
    if (idx < NNODES) {
        int excl = sc[tid] - v + prefix;
        g_rowptr[idx] = excl;
        g_wix[idx] = excl;
    }
    if (bid == SCAN_BLOCKS - 1 && tid == 1023)
        g_rowptr[NNODES] = prefix + total;
}

// ---------------- scatter (clamps bad source, consistent with count) ----------------
__global__ void scatter_kernel(const void* __restrict__ ei) {
    int e = blockIdx.x * blockDim.x + threadIdx.x;
    if (e >= NEDGES) return;
    int s, t;
    if (g_is64) {
        const long long* e64 = (const long long*)ei;
        s = (int)e64[e];
        t = (int)e64[(size_t)NEDGES + e];
    } else {
        const int* e32 = (const int*)ei;
        s = e32[e];
        t = e32[(size_t)NEDGES + e];
    }
    if ((unsigned)t >= NNODES) return;
    if ((unsigned)s >= NNODES) s = 0;   // clamp: keeps slot counts consistent
    int pos = atomicAdd(&g_wix[t], 1);
    g_srcidx[pos] = s;
}

// ---------------- gather aggregation: one warp per node, fp16 rows ----------------
__global__ void gather_kernel(float* __restrict__ out, int phase) {
    int node = (int)(((size_t)blockIdx.x * blockDim.x + threadIdx.x) >> 5);
    int lane = threadIdx.x & 31;
    if (node >= NNODES) return;
    int beg = g_rowptr[node];
    int end = g_rowptr[node + 1];
    const __half* src = (phase == 0) ? g_xh : g_p;

    float a0 = 0.f, a1 = 0.f, a2 = 0.f, a3 = 0.f;
    int i = beg;
    for (; i + 7 < end; i += 8) {
        int sx[8];
#pragma unroll
        for (int u = 0; u < 8; ++u) sx[u] = g_srcidx[i + u];
        uint2 v[8];
#pragma unroll
        for (int u = 0; u < 8; ++u)
            v[u] = *(const uint2*)(src + ((size_t)sx[u] << 7) + lane * 4);
#pragma unroll
        for (int u = 0; u < 8; ++u) {
            float2 f0 = __half22float2(*(const __half2*)&v[u].x);
            float2 f1 = __half22float2(*(const __half2*)&v[u].y);
            a0 += f0.x; a1 += f0.y; a2 += f1.x; a3 += f1.y;
        }
    }
    if (i + 3 < end) {
        int sx[4];
#pragma unroll
        for (int u = 0; u < 4; ++u) sx[u] = g_srcidx[i + u];
        uint2 v[4];
#pragma unroll
        for (int u = 0; u < 4; ++u)
            v[u] = *(const uint2*)(src + ((size_t)sx[u] << 7) + lane * 4);
#pragma unroll
        for (int u = 0; u < 4; ++u) {
            float2 f0 = __half22float2(*(const __half2*)&v[u].x);
            float2 f1 = __half22float2(*(const __half2*)&v[u].y);
            a0 += f0.x; a1 += f0.y; a2 += f1.x; a3 += f1.y;
        }
        i += 4;
    }
    for (; i < end; ++i) {
        uint2 v0 = *(const uint2*)(src + ((size_t)g_srcidx[i] << 7) + lane * 4);
        float2 f0 = __half22float2(*(const __half2*)&v0.x);
        float2 f1 = __half22float2(*(const __half2*)&v0.y);
        a0 += f0.x; a1 += f0.y; a2 += f1.x; a3 += f1.y;
    }
    float rdeg = 1.0f / fmaxf((float)(end - beg), 1.0f);

    if (phase == 0) {
        __half hm[4] = {__float2half(a0 * rdeg), __float2half(a1 * rdeg),
                        __float2half(a2 * rdeg), __float2half(a3 * rdeg)};
        *(uint2*)(g_a + (size_t)node * 256 + lane * 4) = *(const uint2*)hm;
        // fused xsplit: copy x[node] fp16 -> cols [128,256)
        uint2 xr = *(const uint2*)(g_xh + ((size_t)node << 7) + lane * 4);
        *(uint2*)(g_a + (size_t)node * 256 + 128 + lane * 4) = xr;
    } else {
        float4* op = (float4*)out + (size_t)node * 32 + lane;
        float4 o = *op;
        o.x += a0 * rdeg; o.y += a1 * rdeg;
        o.z += a2 * rdeg; o.w += a3 * rdeg;
        *op = o;
    }
}

// ---------------- mma.sync GEMM: single-term fp16 ----------------
#define TILE_B   10240      // 128 * 80
#define STAGE_B  20480
#define GEMM_SMEM 40960

__device__ __forceinline__ void cp_stage(uint32_t sb,
    const __half* A, const __half* W,
    int row0, int nbase, int kt, int st, int tid) {
#pragma unroll
    for (int i = 0; i < 4; ++i) {
        int c = i * 256 + tid;          // 0..1023
        int tile = c >> 9;              // 0:A 1:W
        int idx  = c & 511;
        int row  = idx >> 2;
        int kc   = idx & 3;
        uint32_t dst = sb + st * STAGE_B + tile * TILE_B
                     + (uint32_t)(row * 80 + kc * 16);
        const __half* g = (tile == 0) ? (A + (size_t)(row0 + row) * 256)
                                      : (W + (size_t)(nbase + row) * 256);
        g += kt * 32 + kc * 8;
        CP_ASYNC16(dst, g);
    }
}

__global__ void __launch_bounds__(256, 2) gemm_mma(int layer,
                                                   const float* __restrict__ b1v,
                                                   const float* __restrict__ b2v,
                                                   float* __restrict__ dout) {
    extern __shared__ char dsm[];
    int tid = threadIdx.x, lane = tid & 31, wid = tid >> 5;
    int row0 = blockIdx.x * 128;
    int by   = blockIdx.y;
    int nbase = by * 128;

    const __half* A = (layer == 1) ? g_a : g_b;
    const __half* W = (layer == 1) ? g_w1 : g_w2;

    uint32_t sb = smem_u32(dsm);
    int mrow = (wid >> 1) * 32;
    int ncol = (wid & 1) * 64;

    float acc[2][8][4];
#pragma unroll
    for (int mt = 0; mt < 2; ++mt)
#pragma unroll
        for (int j = 0; j < 8; ++j)
#pragma unroll
            for (int q = 0; q < 4; ++q) acc[mt][j][q] = 0.f;

    cp_stage(sb, A, W, row0, nbase, 0, 0, tid);
    CP_COMMIT();

    for (int kt = 0; kt < 8; ++kt) {
        int st = kt & 1;
        CP_WAIT0();
        __syncthreads();
        if (kt < 7) {
            cp_stage(sb, A, W, row0, nbase, kt + 1, st ^ 1, tid);
            CP_COMMIT();
        }
        const char* sa = dsm + st * STAGE_B;
#pragma unroll
        for (int ks = 0; ks < 2; ++ks) {
            uint32_t a_base = (uint32_t)((mrow + (lane >> 2)) * 80
                                         + (lane & 3) * 4 + ks * 32);
            uint32_t ah[2][4];
#pragma unroll
            for (int mt = 0; mt < 2; ++mt) {
                uint32_t o = a_base + mt * 1280;
                ah[mt][0] = *(const uint32_t*)(sa + o);
                ah[mt][1] = *(const uint32_t*)(sa + o + 640);
                ah[mt][2] = *(const uint32_t*)(sa + o + 16);
                ah[mt][3] = *(const uint32_t*)(sa + o + 656);
            }
            uint32_t b_base = (uint32_t)((ncol + (lane >> 2)) * 80
                                         + (lane & 3) * 4 + ks * 32);
#pragma unroll
            for (int j = 0; j < 8; ++j) {
                uint32_t o = b_base + j * 640;
                uint32_t bh0 = *(const uint32_t*)(sa + TILE_B + o);
                uint32_t bh1 = *(const uint32_t*)(sa + TILE_B + o + 16);
#pragma unroll
                for (int mt = 0; mt < 2; ++mt)
                    MMA_F16(acc[mt][j], ah[mt], bh0, bh1);
            }
        }
        __syncthreads();
    }

    int r_base  = row0 + mrow + (lane >> 2);
    int cl_base = ncol + (lane & 3) * 2;
    if (layer == 1) {
#pragma unroll
        for (int mt = 0; mt < 2; ++mt)
#pragma unroll
            for (int j = 0; j < 8; ++j) {
                int gn = nbase + cl_base + j * 8;
                float bx0 = b1v[gn], bx1 = b1v[gn + 1];
#pragma unroll
                for (int hh = 0; hh < 2; ++hh) {
                    int r = r_base + mt * 16 + hh * 8;
                    float v0 = fmaxf(acc[mt][j][hh * 2]     + bx0, 0.f);
                    float v1 = fmaxf(acc[mt][j][hh * 2 + 1] + bx1, 0.f);
                    __half hp[2] = {__float2half(v0), __float2half(v1)};
                    *(uint32_t*)(g_b + (size_t)r * 256 + gn) = *(const uint32_t*)hp;
                }
            }
    } else {
#pragma unroll
        for (int mt = 0; mt < 2; ++mt)
#pragma unroll
            for (int j = 0; j < 8; ++j) {
                int cl = cl_base + j * 8;
#pragma unroll
                for (int hh = 0; hh < 2; ++hh) {
                    int r = r_base + mt * 16 + hh * 8;
                    float v0 = acc[mt][j][hh * 2];
                    float v1 = acc[mt][j][hh * 2 + 1];
                    if (by == 0) {
                        __half hp[2] = {__float2half(v0), __float2half(v1)};
                        *(uint32_t*)(g_p + (size_t)r * 128 + cl) = *(const uint32_t*)hp;
                    } else if (r < NNODES) {
                        float2 w = make_float2(v0 + b2v[cl], v1 + b2v[cl + 1]);
                        *(float2*)(dout + (size_t)r * 128 + cl) = w;
                    }
                }
            }
    }
}

extern "C" void kernel_launch(void* const* d_in, const int* in_sizes, int n_in,
                              void* d_out, int out_size) {
    const float* x   = (const float*)d_in[0];
    const void*  ei  = d_in[1];
    const float* W1l = (const float*)d_in[2];
    const float* b1  = (const float*)d_in[3];
    const float* W1r = (const float*)d_in[4];
    const float* W2l = (const float*)d_in[5];
    const float* b2  = (const float*)d_in[6];
    const float* W2r = (const float*)d_in[7];
    float* out = (float*)d_out;

    cudaFuncSetAttribute(gemm_mma, cudaFuncAttributeMaxDynamicSharedMemorySize,
                         GEMM_SMEM);

    // 1: detect + zero + xconv + pad + prep (independent parts, one grid)
    mega_prologue<<<MEGA_BLOCKS, 256>>>((const int*)ei, x, W1l, W1r, W2l, W2r);
    // 2-4: CSR build
    count_kernel<<<(NEDGES + 255) / 256, 256>>>(ei);
    scan_lb<<<SCAN_BLOCKS, 1024>>>();
    scatter_kernel<<<(NEDGES + 255) / 256, 256>>>(ei);

    // 5-6: layer 1
    gather_kernel<<<12500, 256>>>(out, 0);
    gemm_mma<<<dim3(NBM, 2), 256, GEMM_SMEM>>>(1, b1, b2, out);

    // 7-8: layer 2
    gemm_mma<<<dim3(NBM, 2), 256, GEMM_SMEM>>>(2, b1, b2, out);
    gather_kernel<<<12500, 256>>>(out, 1);
}